// round 11
// baseline (speedup 1.0000x reference)
#include <cuda_runtime.h>
#include <math.h>

// Problem constants (fixed by the reference)
#define BATCH   2
#define SEQ     2048
#define DMODEL  1024
#define NHEADS  16
#define HDIM    64
#define ROWS    (BATCH * SEQ)        // 4096
#define QKVCOLS (3 * DMODEL)         // 3072

// Scratch (static device globals — allocation-free per harness rules)
__device__ unsigned g_x32[(size_t)ROWS * DMODEL];       // 16 MB (x as tf32 bits)
__device__ unsigned g_qkv[(size_t)ROWS * QKVCOLS];      // 50 MB (tf32 bits; V third unused)
__device__ unsigned g_vT[(size_t)DMODEL * ROWS];        // 16 MB (tf32 bits, [d_global][row])
__device__ unsigned g_att[(size_t)ROWS * DMODEL];       // 16 MB (tf32 bits)
__device__ unsigned g_wqkvT[(size_t)QKVCOLS * DMODEL];  // 12.6 MB (tf32 bits)
__device__ unsigned g_wprojT[(size_t)DMODEL * DMODEL];  // 4.2 MB  (tf32 bits)

// ---------------------------------------------------------------------------
// Helpers
// ---------------------------------------------------------------------------
__device__ __forceinline__ unsigned f2tf32(float x) {
    unsigned r;
    asm("cvt.rna.tf32.f32 %0, %1;" : "=r"(r) : "f"(x));
    return r;
}

// D += A(16x8) * B(8x8), tf32 inputs, fp32 accumulate
#define MMA_TF32(d, a, b)                                                     \
    asm volatile(                                                             \
        "mma.sync.aligned.m16n8k8.row.col.f32.tf32.tf32.f32 "                 \
        "{%0,%1,%2,%3},{%4,%5,%6,%7},{%8,%9},{%0,%1,%2,%3};"                  \
        : "+f"((d)[0]), "+f"((d)[1]), "+f"((d)[2]), "+f"((d)[3])              \
        : "r"((a)[0]), "r"((a)[1]), "r"((a)[2]), "r"((a)[3]),                 \
          "r"((b)[0]), "r"((b)[1]))

#define LDMATRIX_X4(r0, r1, r2, r3, addr)                                     \
    asm volatile(                                                             \
        "ldmatrix.sync.aligned.m8n8.x4.shared.b16 {%0,%1,%2,%3}, [%4];"       \
        : "=r"(r0), "=r"(r1), "=r"(r2), "=r"(r3) : "r"(addr))

__device__ __forceinline__ unsigned smem_u32(const void* p) {
    return (unsigned)__cvta_generic_to_shared(p);
}

__device__ __forceinline__ void cp_async16(unsigned dst, const void* src) {
    asm volatile("cp.async.cg.shared.global [%0], [%1], 16;"
                 :: "r"(dst), "l"(src));
}
#define CP_COMMIT() asm volatile("cp.async.commit_group;")
#define CP_WAIT(n)  asm volatile("cp.async.wait_group %0;" :: "n"(n))

// ---------------------------------------------------------------------------
// x pre-convert: fp32 -> tf32 bits (vectorized, grid-stride)
// ---------------------------------------------------------------------------
__global__ void cvt_x_kernel(const float4* __restrict__ x,
                             uint4* __restrict__ x32, int n4)
{
    int i = blockIdx.x * blockDim.x + threadIdx.x;
    if (i < n4) {
        float4 v = x[i];
        uint4 u;
        u.x = f2tf32(v.x); u.y = f2tf32(v.y);
        u.z = f2tf32(v.z); u.w = f2tf32(v.w);
        x32[i] = u;
    }
}

// ---------------------------------------------------------------------------
// Weight pre-transpose: W[K][N] (f32) -> Wt[N][K] (tf32 bits)
// ---------------------------------------------------------------------------
__global__ void transpose_tf32_kernel(const float* __restrict__ W,
                                      unsigned* __restrict__ Wt,
                                      int K, int N)
{
    __shared__ unsigned t[32][33];
    const int x = blockIdx.x * 32 + threadIdx.x;   // n
    const int y = blockIdx.y * 32;                 // k base
#pragma unroll
    for (int j = threadIdx.y; j < 32; j += 8)
        t[j][threadIdx.x] = f2tf32(W[(size_t)(y + j) * N + x]);
    __syncthreads();
    const int xo = blockIdx.y * 32 + threadIdx.x;  // k
    const int yo = blockIdx.x * 32;                // n base
#pragma unroll
    for (int j = threadIdx.y; j < 32; j += 8)
        Wt[(size_t)(yo + j) * K + xo] = t[threadIdx.x][j];
}

// ---------------------------------------------------------------------------
// TF32 tensor-core GEMM: C[M,N] = A[M,K] @ W[K,N] + bias[N].
// A given as tf32 bits (m-major), Wt as tf32 bits (n-major).
// 3-stage cp.async pipeline, ONE __syncthreads per K-tile, zero cvt/STS in
// the mainloop. OUT_TF32: tf32-bit stores; V-col blocks scatter to vT.
// ---------------------------------------------------------------------------
#define GEMM_STAGE (128 * 36)
#define GEMM_SMEM_BYTES (6 * GEMM_STAGE * 4)

template <bool OUT_TF32>
__global__ __launch_bounds__(256, 2)
void gemm_tf32_kernel(const unsigned* __restrict__ A32,
                      const unsigned* __restrict__ Wt,
                      const float* __restrict__ bias,
                      void* __restrict__ Cv,
                      unsigned* __restrict__ vT,
                      int M, int N, int K)
{
    extern __shared__ unsigned gsm[];
    unsigned* As = gsm;                   // [3][128][36]
    unsigned* Bs = gsm + 3 * GEMM_STAGE;  // [3][128][36]

    const int tid  = threadIdx.x;
    const int lane = tid & 31;
    const int warp = tid >> 5;
    const int wm   = (warp >> 1) * 32;
    const int wn   = (warp & 1) * 64;
    const int row0 = blockIdx.y * 128;
    const int col0 = blockIdx.x * 128;

    float acc[2][8][4];
#pragma unroll
    for (int mt = 0; mt < 2; mt++)
#pragma unroll
        for (int nt = 0; nt < 8; nt++)
#pragma unroll
            for (int c = 0; c < 4; c++) acc[mt][nt][c] = 0.0f;

    // Loader coords: 128 rows x 32 k-cols per stage, 16B per thread x 4 rows
    const int lr = tid >> 3;              // 0..31 (+32p)
    const int lc = (tid & 7) * 4;         // k-col
    const unsigned* Ap = A32 + (size_t)(row0 + lr) * K + lc;
    const unsigned* Bp = Wt  + (size_t)(col0 + lr) * K + lc;
    const unsigned sAb = smem_u32(As);
    const unsigned sBb = smem_u32(Bs);

    // ldmatrix per-lane base addresses
    const unsigned aRow = (lane & 15);
    const unsigned aCol = (lane >> 4) * 4;
    const unsigned a_ldm = sAb + ((wm + aRow) * 36 + aCol) * 4;
    const unsigned bRow = (lane & 7) + ((lane & 16) >> 1);
    const unsigned bCol = (lane & 8) ? 4u : 0u;
    const unsigned b_ldm = sBb + ((wn + bRow) * 36 + bCol) * 4;

    const int NT = K / 32;                // 32 K-tiles

    // Prologue: issue tiles 0 and 1 into stages 0 and 1
#pragma unroll
    for (int t = 0; t < 2; t++) {
#pragma unroll
        for (int p = 0; p < 4; p++) {
            cp_async16(sAb + (t * GEMM_STAGE + (lr + p * 32) * 36 + lc) * 4,
                       Ap + t * 32 + (size_t)(p * 32) * K);
            cp_async16(sBb + (t * GEMM_STAGE + (lr + p * 32) * 36 + lc) * 4,
                       Bp + t * 32 + (size_t)(p * 32) * K);
        }
        CP_COMMIT();
    }

    for (int i = 0; i < NT; i++) {
        if (i + 1 < NT) { CP_WAIT(1); } else { CP_WAIT(0); }
        __syncthreads();

        // Issue tile i+2 into stage (i+2)%3 (that stage's compute finished
        // at iter i-1; the sync above makes its reuse safe)
        if (i + 2 < NT) {
            const int s = (i + 2) % 3;
            const int t = (i + 2) * 32;
#pragma unroll
            for (int p = 0; p < 4; p++) {
                cp_async16(sAb + (s * GEMM_STAGE + (lr + p * 32) * 36 + lc) * 4,
                           Ap + t + (size_t)(p * 32) * K);
                cp_async16(sBb + (s * GEMM_STAGE + (lr + p * 32) * 36 + lc) * 4,
                           Bp + t + (size_t)(p * 32) * K);
            }
            CP_COMMIT();
        }

        const unsigned aBuf = a_ldm + (i % 3) * GEMM_STAGE * 4;
        const unsigned bBuf = b_ldm + (i % 3) * GEMM_STAGE * 4;
#pragma unroll
        for (int ks = 0; ks < 4; ks++) {
            const int k8 = ks * 8;
            unsigned af[2][4];
#pragma unroll
            for (int mt = 0; mt < 2; mt++)
                LDMATRIX_X4(af[mt][0], af[mt][1], af[mt][2], af[mt][3],
                            aBuf + (mt * 16 * 36 + k8) * 4);
            unsigned bf[8][2];
#pragma unroll
            for (int ntp = 0; ntp < 4; ntp++)
                LDMATRIX_X4(bf[2 * ntp][0], bf[2 * ntp][1],
                            bf[2 * ntp + 1][0], bf[2 * ntp + 1][1],
                            bBuf + (ntp * 16 * 36 + k8) * 4);
#pragma unroll
            for (int mt = 0; mt < 2; mt++)
#pragma unroll
                for (int nt = 0; nt < 8; nt++)
                    MMA_TF32(acc[mt][nt], af[mt], bf[nt]);
        }
    }

    // Epilogue: bias + stores
    const int g  = lane >> 2;
    const int t4 = lane & 3;
    const bool isV = OUT_TF32 && (col0 >= 2 * DMODEL);
#pragma unroll
    for (int mt = 0; mt < 2; mt++) {
        const int rA = row0 + wm + mt * 16 + g;
#pragma unroll
        for (int nt = 0; nt < 8; nt++) {
            const int c = col0 + wn + nt * 8 + 2 * t4;
            const float2 bv = *(const float2*)&bias[c];
            if (OUT_TF32) {
                if (isV) {
                    // transposed store: vT[d_global][row]
                    const int c2 = c - 2 * DMODEL;
                    vT[(size_t)c2 * ROWS + rA]           = f2tf32(acc[mt][nt][0] + bv.x);
                    vT[(size_t)(c2 + 1) * ROWS + rA]     = f2tf32(acc[mt][nt][1] + bv.y);
                    vT[(size_t)c2 * ROWS + rA + 8]       = f2tf32(acc[mt][nt][2] + bv.x);
                    vT[(size_t)(c2 + 1) * ROWS + rA + 8] = f2tf32(acc[mt][nt][3] + bv.y);
                } else {
                    unsigned* C = (unsigned*)Cv;
                    uint2 o0, o1;
                    o0.x = f2tf32(acc[mt][nt][0] + bv.x);
                    o0.y = f2tf32(acc[mt][nt][1] + bv.y);
                    o1.x = f2tf32(acc[mt][nt][2] + bv.x);
                    o1.y = f2tf32(acc[mt][nt][3] + bv.y);
                    *(uint2*)&C[(size_t)rA * N + c] = o0;
                    *(uint2*)&C[(size_t)(rA + 8) * N + c] = o1;
                }
            } else {
                float* C = (float*)Cv;
                float2 o0, o1;
                o0.x = acc[mt][nt][0] + bv.x;
                o0.y = acc[mt][nt][1] + bv.y;
                o1.x = acc[mt][nt][2] + bv.x;
                o1.y = acc[mt][nt][3] + bv.y;
                *(float2*)&C[(size_t)rA * N + c] = o0;
                *(float2*)&C[(size_t)(rA + 8) * N + c] = o1;
            }
        }
    }
}

// ---------------------------------------------------------------------------
// Flash attention: BQ=128, BK=64, 8 warps; Q,K from qkv (tf32 bits),
// V from vT[d_global][row] (tf32 bits, n-major -> ldmatrix b-frags).
// cp.async double-buffered K/V. Output stored as tf32 bits (proj consumes).
//   sK[2][64][68], sVt[2][64][68] (rows=d, cols=token), sP[128][68]
// ---------------------------------------------------------------------------
#define SKT (64 * 68)
#define SMEM_ATT_BYTES ((4 * SKT + 128 * 68) * 4)

__global__ __launch_bounds__(256, 2)
void flash_attn_tf32_kernel(const unsigned* __restrict__ qkv,
                            const unsigned* __restrict__ vT,
                            unsigned* __restrict__ att)
{
    extern __shared__ unsigned asm_[];
    unsigned* sK  = asm_;                // [2][64][68]
    unsigned* sVt = sK + 2 * SKT;        // [2][64][68] rows=d, cols=token
    unsigned* sP  = sVt + 2 * SKT;       // [128][68]   (Q staging, then P)

    const int tid  = threadIdx.x;
    const int lane = tid & 31;
    const int warp = tid >> 5;           // 0..7 -> rows [16w,16w+16)
    const int g    = lane >> 2;
    const int t4   = lane & 3;
    const int wr   = warp * 16;

    const int bh = blockIdx.y;
    const int b  = bh / NHEADS;
    const int h  = bh % NHEADS;
    const int qt = gridDim.x - 1 - blockIdx.x;   // heavy tiles first
    const int q0 = qt * 128;

    const size_t rowbase = (size_t)b * SEQ;
    const int qcol = h * HDIM;
    const int kcol = DMODEL + h * HDIM;
    const unsigned* vTh = vT + (size_t)h * HDIM * ROWS + rowbase;

    // ldmatrix base addresses (same lane mapping for K and Vt)
    const unsigned nRow = (lane & 7) + ((lane & 16) >> 1);
    const unsigned nColOff = (lane & 8) ? 4u : 0u;
    const unsigned k_ldm = smem_u32(sK)  + (nRow * 68 + nColOff) * 4;
    const unsigned v_ldm = smem_u32(sVt) + (nRow * 68 + nColOff) * 4;
    const unsigned pRow = wr + (lane & 15);
    const unsigned pColOff = (lane >> 4) * 4;
    const unsigned p_ldm = smem_u32(sP) + (pRow * 68 + pColOff) * 4;

    // Loader coords (16B per thread per pass; 4 passes cover 64x64)
    const int lvr = tid >> 4;            // 0..15 (+16 per pass)
    const int lvc = (tid & 15) * 4;      // 0..60
    const unsigned sKb = smem_u32(sK);
    const unsigned sVb = smem_u32(sVt);

    // ---- Stage Q tile into sP (raw tf32 bits) ----
    for (int i = tid; i < 128 * 16; i += 256) {
        const int r  = i >> 4;
        const int c4 = (i & 15) * 4;
        *(uint4*)&sP[r * 68 + c4] =
            *(const uint4*)&qkv[(rowbase + q0 + r) * QKVCOLS + qcol + c4];
    }

    // ---- Prologue: async-load K/V tile 0 into buffer 0 ----
    {
#pragma unroll
        for (int p = 0; p < 4; p++) {
            const int r = lvr + p * 16;
            cp_async16(sKb + (r * 68 + lvc) * 4,
                       &qkv[(rowbase + r) * QKVCOLS + kcol + lvc]);
            cp_async16(sVb + (r * 68 + lvc) * 4,
                       &vTh[(size_t)r * ROWS + lvc]);
        }
        CP_COMMIT();
    }
    __syncthreads();   // sP (Q) visible to all warps

    // Q a-frags via ldmatrix
    unsigned qf[8][4];
#pragma unroll
    for (int ks = 0; ks < 8; ks++)
        LDMATRIX_X4(qf[ks][0], qf[ks][1], qf[ks][2], qf[ks][3],
                    p_ldm + ks * 8 * 4);

    float m0 = -1e30f, m1 = -1e30f, l0 = 0.0f, l1 = 0.0f;
    float o[8][4];
#pragma unroll
    for (int nt = 0; nt < 8; nt++)
#pragma unroll
        for (int c = 0; c < 4; c++) o[nt][c] = 0.0f;

    const int n_kt = 2 * qt + 2;
    for (int kt = 0; kt < n_kt; kt++) {
        const int buf = kt & 1;

        // Issue next tile's loads into the other buffer
        if (kt + 1 < n_kt) {
            const int k0n = (kt + 1) * 64;
            const unsigned sKn = sKb + (buf ^ 1) * SKT * 4;
            const unsigned sVn = sVb + (buf ^ 1) * SKT * 4;
#pragma unroll
            for (int p = 0; p < 4; p++) {
                const int r = lvr + p * 16;
                cp_async16(sKn + (r * 68 + lvc) * 4,
                           &qkv[(rowbase + k0n + r) * QKVCOLS + kcol + lvc]);
                cp_async16(sVn + (r * 68 + lvc) * 4,
                           &vTh[(size_t)r * ROWS + k0n + lvc]);
            }
            CP_COMMIT();
            CP_WAIT(1);
        } else {
            CP_WAIT(0);
        }
        __syncthreads();

        const int k0 = kt * 64;
        if (q0 + wr + 15 >= k0) {
            const unsigned kb = k_ldm + buf * SKT * 4;
            const unsigned vb = v_ldm + buf * SKT * 4;

            // ---- S = Q @ K^T ----
            float s[8][4];
#pragma unroll
            for (int nt = 0; nt < 8; nt++)
#pragma unroll
                for (int c = 0; c < 4; c++) s[nt][c] = 0.0f;
#pragma unroll
            for (int ks = 0; ks < 8; ks++) {
                const int k8 = ks * 8;
                unsigned bf[8][2];
#pragma unroll
                for (int ntp = 0; ntp < 4; ntp++)
                    LDMATRIX_X4(bf[2 * ntp][0], bf[2 * ntp][1],
                                bf[2 * ntp + 1][0], bf[2 * ntp + 1][1],
                                kb + (ntp * 16 * 68 + k8) * 4);
#pragma unroll
                for (int nt = 0; nt < 8; nt++)
                    MMA_TF32(s[nt], qf[ks], bf[nt]);
            }

            // ---- Scale + causal mask ----
            const bool diag = (kt >= 2 * qt);
            const int rg0 = q0 + wr + g;
            const int rg1 = rg0 + 8;
#pragma unroll
            for (int nt = 0; nt < 8; nt++) {
                const int cg = k0 + nt * 8 + 2 * t4;
                s[nt][0] *= 0.125f; s[nt][1] *= 0.125f;
                s[nt][2] *= 0.125f; s[nt][3] *= 0.125f;
                if (diag) {
                    if (cg > rg0)     s[nt][0] = -1e9f;
                    if (cg + 1 > rg0) s[nt][1] = -1e9f;
                    if (cg > rg1)     s[nt][2] = -1e9f;
                    if (cg + 1 > rg1) s[nt][3] = -1e9f;
                }
            }

            // ---- Online softmax in registers ----
            float mx0 = -1e30f, mx1 = -1e30f;
#pragma unroll
            for (int nt = 0; nt < 8; nt++) {
                mx0 = fmaxf(mx0, fmaxf(s[nt][0], s[nt][1]));
                mx1 = fmaxf(mx1, fmaxf(s[nt][2], s[nt][3]));
            }
            mx0 = fmaxf(mx0, __shfl_xor_sync(0xffffffffu, mx0, 1));
            mx0 = fmaxf(mx0, __shfl_xor_sync(0xffffffffu, mx0, 2));
            mx1 = fmaxf(mx1, __shfl_xor_sync(0xffffffffu, mx1, 1));
            mx1 = fmaxf(mx1, __shfl_xor_sync(0xffffffffu, mx1, 2));

            const float m0n = fmaxf(m0, mx0);
            const float m1n = fmaxf(m1, mx1);
            const float al0 = __expf(m0 - m0n);
            const float al1 = __expf(m1 - m1n);

            float sum0 = 0.0f, sum1 = 0.0f;
#pragma unroll
            for (int nt = 0; nt < 8; nt++) {
                s[nt][0] = __expf(s[nt][0] - m0n);
                s[nt][1] = __expf(s[nt][1] - m0n);
                s[nt][2] = __expf(s[nt][2] - m1n);
                s[nt][3] = __expf(s[nt][3] - m1n);
                sum0 += s[nt][0] + s[nt][1];
                sum1 += s[nt][2] + s[nt][3];
            }
            sum0 += __shfl_xor_sync(0xffffffffu, sum0, 1);
            sum0 += __shfl_xor_sync(0xffffffffu, sum0, 2);
            sum1 += __shfl_xor_sync(0xffffffffu, sum1, 1);
            sum1 += __shfl_xor_sync(0xffffffffu, sum1, 2);

            l0 = l0 * al0 + sum0;
            l1 = l1 * al1 + sum1;
            m0 = m0n; m1 = m1n;

#pragma unroll
            for (int nt = 0; nt < 8; nt++) {
                o[nt][0] *= al0; o[nt][1] *= al0;
                o[nt][2] *= al1; o[nt][3] *= al1;
            }

            // ---- Stage P (tf32) in warp-private sP rows ----
#pragma unroll
            for (int nt = 0; nt < 8; nt++) {
                const int c2 = nt * 8 + 2 * t4;
                sP[(wr + g) * 68 + c2]     = f2tf32(s[nt][0]);
                sP[(wr + g) * 68 + c2 + 1] = f2tf32(s[nt][1]);
                sP[(wr + g + 8) * 68 + c2]     = f2tf32(s[nt][2]);
                sP[(wr + g + 8) * 68 + c2 + 1] = f2tf32(s[nt][3]);
            }
            __syncwarp();

            // ---- O += P @ V  (V b-frags via ldmatrix on sVt) ----
#pragma unroll
            for (int ks = 0; ks < 8; ks++) {
                const int k8 = ks * 8;
                unsigned a[4];
                LDMATRIX_X4(a[0], a[1], a[2], a[3], p_ldm + k8 * 4);
                unsigned bf[8][2];
#pragma unroll
                for (int ntp = 0; ntp < 4; ntp++)
                    LDMATRIX_X4(bf[2 * ntp][0], bf[2 * ntp][1],
                                bf[2 * ntp + 1][0], bf[2 * ntp + 1][1],
                                vb + (ntp * 16 * 68 + k8) * 4);
#pragma unroll
                for (int nt = 0; nt < 8; nt++)
                    MMA_TF32(o[nt], a, bf[nt]);
            }
        }
        __syncthreads();
    }

    // ---- Normalize and store merged-head output as tf32 bits ----
    const float inv0 = 1.0f / l0;
    const float inv1 = 1.0f / l1;
    const size_t r0 = rowbase + q0 + wr + g;
#pragma unroll
    for (int nt = 0; nt < 8; nt++) {
        const int col = h * HDIM + nt * 8 + 2 * t4;
        uint2 v0, v1;
        v0.x = f2tf32(o[nt][0] * inv0); v0.y = f2tf32(o[nt][1] * inv0);
        v1.x = f2tf32(o[nt][2] * inv1); v1.y = f2tf32(o[nt][3] * inv1);
        *(uint2*)&att[r0 * DMODEL + col] = v0;
        *(uint2*)&att[(r0 + 8) * DMODEL + col] = v1;
    }
}

// ---------------------------------------------------------------------------
// Launch
// ---------------------------------------------------------------------------
extern "C" void kernel_launch(void* const* d_in, const int* in_sizes, int n_in,
                              void* d_out, int out_size)
{
    const float* x      = (const float*)d_in[0];  // [2,2048,1024]
    const float* W_qkv  = (const float*)d_in[1];  // [1024,3072]
    const float* b_qkv  = (const float*)d_in[2];  // [3072]
    const float* W_proj = (const float*)d_in[3];  // [1024,1024]
    const float* b_proj = (const float*)d_in[4];  // [1024]
    float* out          = (float*)d_out;          // [2,2048,1024]

    unsigned *x32_buf, *qkv_buf, *vT_buf, *att_buf, *wqkvT, *wprojT;
    cudaGetSymbolAddress((void**)&x32_buf, g_x32);
    cudaGetSymbolAddress((void**)&qkv_buf, g_qkv);
    cudaGetSymbolAddress((void**)&vT_buf,  g_vT);
    cudaGetSymbolAddress((void**)&att_buf, g_att);
    cudaGetSymbolAddress((void**)&wqkvT,  g_wqkvT);
    cudaGetSymbolAddress((void**)&wprojT, g_wprojT);

    cudaFuncSetAttribute(gemm_tf32_kernel<true>,
                         cudaFuncAttributeMaxDynamicSharedMemorySize,
                         GEMM_SMEM_BYTES);
    cudaFuncSetAttribute(gemm_tf32_kernel<false>,
                         cudaFuncAttributeMaxDynamicSharedMemorySize,
                         GEMM_SMEM_BYTES);
    cudaFuncSetAttribute(flash_attn_tf32_kernel,
                         cudaFuncAttributeMaxDynamicSharedMemorySize,
                         SMEM_ATT_BYTES);

    // 0) Pre-convert x to tf32 bits; pre-transpose weights to tf32 n-major
    {
        const int n4 = ROWS * DMODEL / 4;
        cvt_x_kernel<<<(n4 + 255) / 256, 256>>>(
            (const float4*)x, (uint4*)x32_buf, n4);
        dim3 blk(32, 8);
        dim3 g1(QKVCOLS / 32, DMODEL / 32);
        transpose_tf32_kernel<<<g1, blk>>>(W_qkv, wqkvT, DMODEL, QKVCOLS);
        dim3 g2(DMODEL / 32, DMODEL / 32);
        transpose_tf32_kernel<<<g2, blk>>>(W_proj, wprojT, DMODEL, DMODEL);
    }

    // 1) QKV projection -> tf32 qkv buffer (Q,K) + transposed V buffer
    {
        dim3 grid(QKVCOLS / 128, ROWS / 128);
        gemm_tf32_kernel<true><<<grid, 256, GEMM_SMEM_BYTES>>>(
            x32_buf, wqkvT, b_qkv, qkv_buf, vT_buf, ROWS, QKVCOLS, DMODEL);
    }

    // 2) Causal flash attention -> tf32 att buffer
    {
        dim3 grid(SEQ / 128, BATCH * NHEADS);
        flash_attn_tf32_kernel<<<grid, 256, SMEM_ATT_BYTES>>>(
            qkv_buf, vT_buf, att_buf);
    }

    // 3) Output projection -> fp32 out
    {
        dim3 grid(DMODEL / 128, ROWS / 128);
        gemm_tf32_kernel<false><<<grid, 256, GEMM_SMEM_BYTES>>>(
            att_buf, wprojT, b_proj, out, nullptr, ROWS, DMODEL, DMODEL);
    }
}

// round 13
// speedup vs baseline: 1.0185x; 1.0185x over previous
#include <cuda_runtime.h>
#include <math.h>

// Problem constants (fixed by the reference)
#define BATCH   2
#define SEQ     2048
#define DMODEL  1024
#define NHEADS  16
#define HDIM    64
#define ROWS    (BATCH * SEQ)        // 4096
#define QKVCOLS (3 * DMODEL)         // 3072

// Scratch (static device globals — allocation-free per harness rules)
__device__ unsigned g_x32[(size_t)ROWS * DMODEL];       // 16 MB (x as tf32 bits)
__device__ unsigned g_qkv[(size_t)ROWS * QKVCOLS];      // 50 MB (tf32 bits; V third unused)
__device__ unsigned g_vT[(size_t)DMODEL * ROWS];        // 16 MB (tf32 bits, [d_global][row])
__device__ unsigned g_att[(size_t)ROWS * DMODEL];       // 16 MB (tf32 bits)
__device__ unsigned g_wqkvT[(size_t)QKVCOLS * DMODEL];  // 12.6 MB (tf32 bits)
__device__ unsigned g_wprojT[(size_t)DMODEL * DMODEL];  // 4.2 MB  (tf32 bits)

// ---------------------------------------------------------------------------
// Helpers
// ---------------------------------------------------------------------------
__device__ __forceinline__ unsigned f2tf32(float x) {
    unsigned r;
    asm("cvt.rna.tf32.f32 %0, %1;" : "=r"(r) : "f"(x));
    return r;
}

// D += A(16x8) * B(8x8), tf32 inputs, fp32 accumulate
#define MMA_TF32(d, a, b)                                                     \
    asm volatile(                                                             \
        "mma.sync.aligned.m16n8k8.row.col.f32.tf32.tf32.f32 "                 \
        "{%0,%1,%2,%3},{%4,%5,%6,%7},{%8,%9},{%0,%1,%2,%3};"                  \
        : "+f"((d)[0]), "+f"((d)[1]), "+f"((d)[2]), "+f"((d)[3])              \
        : "r"((a)[0]), "r"((a)[1]), "r"((a)[2]), "r"((a)[3]),                 \
          "r"((b)[0]), "r"((b)[1]))

#define LDMATRIX_X4(r0, r1, r2, r3, addr)                                     \
    asm volatile(                                                             \
        "ldmatrix.sync.aligned.m8n8.x4.shared.b16 {%0,%1,%2,%3}, [%4];"       \
        : "=r"(r0), "=r"(r1), "=r"(r2), "=r"(r3) : "r"(addr))

__device__ __forceinline__ unsigned smem_u32(const void* p) {
    return (unsigned)__cvta_generic_to_shared(p);
}

__device__ __forceinline__ void cp_async16(unsigned dst, const void* src) {
    asm volatile("cp.async.cg.shared.global [%0], [%1], 16;"
                 :: "r"(dst), "l"(src));
}
#define CP_COMMIT() asm volatile("cp.async.commit_group;")
#define CP_WAIT(n)  asm volatile("cp.async.wait_group %0;" :: "n"(n))

// ---------------------------------------------------------------------------
// x pre-convert: fp32 -> tf32 bits (vectorized)
// ---------------------------------------------------------------------------
__global__ void cvt_x_kernel(const float4* __restrict__ x,
                             uint4* __restrict__ x32, int n4)
{
    int i = blockIdx.x * blockDim.x + threadIdx.x;
    if (i < n4) {
        float4 v = x[i];
        uint4 u;
        u.x = f2tf32(v.x); u.y = f2tf32(v.y);
        u.z = f2tf32(v.z); u.w = f2tf32(v.w);
        x32[i] = u;
    }
}

// ---------------------------------------------------------------------------
// Weight pre-transpose: W[K][N] (f32) -> Wt[N][K] (tf32 bits)
// ---------------------------------------------------------------------------
__global__ void transpose_tf32_kernel(const float* __restrict__ W,
                                      unsigned* __restrict__ Wt,
                                      int K, int N)
{
    __shared__ unsigned t[32][33];
    const int x = blockIdx.x * 32 + threadIdx.x;   // n
    const int y = blockIdx.y * 32;                 // k base
#pragma unroll
    for (int j = threadIdx.y; j < 32; j += 8)
        t[j][threadIdx.x] = f2tf32(W[(size_t)(y + j) * N + x]);
    __syncthreads();
    const int xo = blockIdx.y * 32 + threadIdx.x;  // k
    const int yo = blockIdx.x * 32;                // n base
#pragma unroll
    for (int j = threadIdx.y; j < 32; j += 8)
        Wt[(size_t)(yo + j) * K + xo] = t[threadIdx.x][j];
}

// ---------------------------------------------------------------------------
// TF32 tensor-core GEMM: C[M,N] = A[M,K] @ W[K,N] + bias[N].
// A32 (tf32 bits, m-major), Wt (tf32 bits, n-major) — loader is raw uint4
// copies, zero cvt. R8-style register-staged double buffer: LDG next tile
// into regs, mma current, STS regs, ONE __syncthreads per K-tile (ptxas
// interleaves the LDGs with the mma stream — beats the cp.async wait
// pipeline that collapsed issue to 17.6% in R11).
// ---------------------------------------------------------------------------
#define GEMM_BUF   (128 * 36)
#define GEMM_SMEM_BYTES (4 * GEMM_BUF * 4)

template <bool OUT_TF32>
__global__ __launch_bounds__(256, 2)
void gemm_tf32_kernel(const unsigned* __restrict__ A32,
                      const unsigned* __restrict__ Wt,
                      const float* __restrict__ bias,
                      void* __restrict__ Cv,
                      unsigned* __restrict__ vT,
                      int M, int N, int K)
{
    extern __shared__ unsigned gsm[];
    unsigned* As = gsm;                  // [2][128][36]
    unsigned* Bs = gsm + 2 * GEMM_BUF;   // [2][128][36]

    const int tid  = threadIdx.x;
    const int lane = tid & 31;
    const int warp = tid >> 5;
    const int wm   = (warp >> 1) * 32;
    const int wn   = (warp & 1) * 64;
    const int row0 = blockIdx.y * 128;
    const int col0 = blockIdx.x * 128;

    float acc[2][8][4];
#pragma unroll
    for (int mt = 0; mt < 2; mt++)
#pragma unroll
        for (int nt = 0; nt < 8; nt++)
#pragma unroll
            for (int c = 0; c < 4; c++) acc[mt][nt][c] = 0.0f;

    const int lr = tid >> 3;             // 0..31 (+32p)
    const int lc = (tid & 7) * 4;        // k-col
    const unsigned* Ap = A32 + (size_t)(row0 + lr) * K + lc;
    const unsigned* Bp = Wt  + (size_t)(col0 + lr) * K + lc;

    const unsigned aRow = (lane & 15);
    const unsigned aCol = (lane >> 4) * 4;
    const unsigned a_ldm = smem_u32(As) + ((wm + aRow) * 36 + aCol) * 4;
    const unsigned bRow = (lane & 7) + ((lane & 16) >> 1);
    const unsigned bCol = (lane & 8) ? 4u : 0u;
    const unsigned b_ldm = smem_u32(Bs) + ((wn + bRow) * 36 + bCol) * 4;

    // Load first K-tile into buffer 0 (raw copies)
    {
#pragma unroll
        for (int p = 0; p < 4; p++) {
            *(uint4*)&As[(lr + p * 32) * 36 + lc] =
                *(const uint4*)(Ap + (size_t)(p * 32) * K);
            *(uint4*)&Bs[(lr + p * 32) * 36 + lc] =
                *(const uint4*)(Bp + (size_t)(p * 32) * K);
        }
    }
    __syncthreads();

    int cur = 0;
    for (int k0 = 0; k0 < K; k0 += 32) {
        const int k1 = k0 + 32;
        uint4 stA[4], stB[4];
        if (k1 < K) {
#pragma unroll
            for (int p = 0; p < 4; p++) {
                stA[p] = *(const uint4*)(Ap + k1 + (size_t)(p * 32) * K);
                stB[p] = *(const uint4*)(Bp + k1 + (size_t)(p * 32) * K);
            }
        }

        const unsigned aBuf = a_ldm + cur * GEMM_BUF * 4;
        const unsigned bBuf = b_ldm + cur * GEMM_BUF * 4;
#pragma unroll
        for (int ks = 0; ks < 4; ks++) {
            const int k8 = ks * 8;
            unsigned af[2][4];
#pragma unroll
            for (int mt = 0; mt < 2; mt++)
                LDMATRIX_X4(af[mt][0], af[mt][1], af[mt][2], af[mt][3],
                            aBuf + (mt * 16 * 36 + k8) * 4);
            unsigned bf[8][2];
#pragma unroll
            for (int ntp = 0; ntp < 4; ntp++)
                LDMATRIX_X4(bf[2 * ntp][0], bf[2 * ntp][1],
                            bf[2 * ntp + 1][0], bf[2 * ntp + 1][1],
                            bBuf + (ntp * 16 * 36 + k8) * 4);
#pragma unroll
            for (int mt = 0; mt < 2; mt++)
#pragma unroll
                for (int nt = 0; nt < 8; nt++)
                    MMA_TF32(acc[mt][nt], af[mt], bf[nt]);
        }

        if (k1 < K) {
            unsigned* An = As + (cur ^ 1) * GEMM_BUF;
            unsigned* Bn = Bs + (cur ^ 1) * GEMM_BUF;
#pragma unroll
            for (int p = 0; p < 4; p++) {
                *(uint4*)&An[(lr + p * 32) * 36 + lc] = stA[p];
                *(uint4*)&Bn[(lr + p * 32) * 36 + lc] = stB[p];
            }
        }
        __syncthreads();
        cur ^= 1;
    }

    // Epilogue: bias + stores
    const int g  = lane >> 2;
    const int t4 = lane & 3;
    const bool isV = OUT_TF32 && (col0 >= 2 * DMODEL);
#pragma unroll
    for (int mt = 0; mt < 2; mt++) {
        const int rA = row0 + wm + mt * 16 + g;
#pragma unroll
        for (int nt = 0; nt < 8; nt++) {
            const int c = col0 + wn + nt * 8 + 2 * t4;
            const float2 bv = *(const float2*)&bias[c];
            if (OUT_TF32) {
                if (isV) {
                    // transposed store: vT[d_global][row]
                    const int c2 = c - 2 * DMODEL;
                    vT[(size_t)c2 * ROWS + rA]           = f2tf32(acc[mt][nt][0] + bv.x);
                    vT[(size_t)(c2 + 1) * ROWS + rA]     = f2tf32(acc[mt][nt][1] + bv.y);
                    vT[(size_t)c2 * ROWS + rA + 8]       = f2tf32(acc[mt][nt][2] + bv.x);
                    vT[(size_t)(c2 + 1) * ROWS + rA + 8] = f2tf32(acc[mt][nt][3] + bv.y);
                } else {
                    unsigned* C = (unsigned*)Cv;
                    uint2 o0, o1;
                    o0.x = f2tf32(acc[mt][nt][0] + bv.x);
                    o0.y = f2tf32(acc[mt][nt][1] + bv.y);
                    o1.x = f2tf32(acc[mt][nt][2] + bv.x);
                    o1.y = f2tf32(acc[mt][nt][3] + bv.y);
                    *(uint2*)&C[(size_t)rA * N + c] = o0;
                    *(uint2*)&C[(size_t)(rA + 8) * N + c] = o1;
                }
            } else {
                float* C = (float*)Cv;
                float2 o0, o1;
                o0.x = acc[mt][nt][0] + bv.x;
                o0.y = acc[mt][nt][1] + bv.y;
                o1.x = acc[mt][nt][2] + bv.x;
                o1.y = acc[mt][nt][3] + bv.y;
                *(float2*)&C[(size_t)rA * N + c] = o0;
                *(float2*)&C[(size_t)(rA + 8) * N + c] = o1;
            }
        }
    }
}

// ---------------------------------------------------------------------------
// Flash attention: BQ=128, BK=64, 8 warps; Q,K from qkv (tf32 bits),
// V from vT[d_global][row] (tf32 bits, n-major -> ldmatrix b-frags).
// cp.async double-buffered K/V. Output stored as tf32 bits (proj consumes).
//   sK[2][64][68], sVt[2][64][68] (rows=d, cols=token), sP[128][68]
// ---------------------------------------------------------------------------
#define SKT (64 * 68)
#define SMEM_ATT_BYTES ((4 * SKT + 128 * 68) * 4)

__global__ __launch_bounds__(256, 2)
void flash_attn_tf32_kernel(const unsigned* __restrict__ qkv,
                            const unsigned* __restrict__ vT,
                            unsigned* __restrict__ att)
{
    extern __shared__ unsigned asm_[];
    unsigned* sK  = asm_;                // [2][64][68]
    unsigned* sVt = sK + 2 * SKT;        // [2][64][68] rows=d, cols=token
    unsigned* sP  = sVt + 2 * SKT;       // [128][68]   (Q staging, then P)

    const int tid  = threadIdx.x;
    const int lane = tid & 31;
    const int warp = tid >> 5;           // 0..7 -> rows [16w,16w+16)
    const int g    = lane >> 2;
    const int t4   = lane & 3;
    const int wr   = warp * 16;

    const int bh = blockIdx.y;
    const int b  = bh / NHEADS;
    const int h  = bh % NHEADS;
    const int qt = gridDim.x - 1 - blockIdx.x;   // heavy tiles first
    const int q0 = qt * 128;

    const size_t rowbase = (size_t)b * SEQ;
    const int qcol = h * HDIM;
    const int kcol = DMODEL + h * HDIM;
    const unsigned* vTh = vT + (size_t)h * HDIM * ROWS + rowbase;

    // ldmatrix base addresses (same lane mapping for K and Vt)
    const unsigned nRow = (lane & 7) + ((lane & 16) >> 1);
    const unsigned nColOff = (lane & 8) ? 4u : 0u;
    const unsigned k_ldm = smem_u32(sK)  + (nRow * 68 + nColOff) * 4;
    const unsigned v_ldm = smem_u32(sVt) + (nRow * 68 + nColOff) * 4;
    const unsigned pRow = wr + (lane & 15);
    const unsigned pColOff = (lane >> 4) * 4;
    const unsigned p_ldm = smem_u32(sP) + (pRow * 68 + pColOff) * 4;

    // Loader coords (16B per thread per pass; 4 passes cover 64x64)
    const int lvr = tid >> 4;            // 0..15 (+16 per pass)
    const int lvc = (tid & 15) * 4;      // 0..60
    const unsigned sKb = smem_u32(sK);
    const unsigned sVb = smem_u32(sVt);

    // ---- Stage Q tile into sP (raw tf32 bits) ----
    for (int i = tid; i < 128 * 16; i += 256) {
        const int r  = i >> 4;
        const int c4 = (i & 15) * 4;
        *(uint4*)&sP[r * 68 + c4] =
            *(const uint4*)&qkv[(rowbase + q0 + r) * QKVCOLS + qcol + c4];
    }

    // ---- Prologue: async-load K/V tile 0 into buffer 0 ----
    {
#pragma unroll
        for (int p = 0; p < 4; p++) {
            const int r = lvr + p * 16;
            cp_async16(sKb + (r * 68 + lvc) * 4,
                       &qkv[(rowbase + r) * QKVCOLS + kcol + lvc]);
            cp_async16(sVb + (r * 68 + lvc) * 4,
                       &vTh[(size_t)r * ROWS + lvc]);
        }
        CP_COMMIT();
    }
    __syncthreads();   // sP (Q) visible to all warps

    // Q a-frags via ldmatrix
    unsigned qf[8][4];
#pragma unroll
    for (int ks = 0; ks < 8; ks++)
        LDMATRIX_X4(qf[ks][0], qf[ks][1], qf[ks][2], qf[ks][3],
                    p_ldm + ks * 8 * 4);

    float m0 = -1e30f, m1 = -1e30f, l0 = 0.0f, l1 = 0.0f;
    float o[8][4];
#pragma unroll
    for (int nt = 0; nt < 8; nt++)
#pragma unroll
        for (int c = 0; c < 4; c++) o[nt][c] = 0.0f;

    const int n_kt = 2 * qt + 2;
    for (int kt = 0; kt < n_kt; kt++) {
        const int buf = kt & 1;

        // Issue next tile's loads into the other buffer
        if (kt + 1 < n_kt) {
            const int k0n = (kt + 1) * 64;
            const unsigned sKn = sKb + (buf ^ 1) * SKT * 4;
            const unsigned sVn = sVb + (buf ^ 1) * SKT * 4;
#pragma unroll
            for (int p = 0; p < 4; p++) {
                const int r = lvr + p * 16;
                cp_async16(sKn + (r * 68 + lvc) * 4,
                           &qkv[(rowbase + k0n + r) * QKVCOLS + kcol + lvc]);
                cp_async16(sVn + (r * 68 + lvc) * 4,
                           &vTh[(size_t)r * ROWS + k0n + lvc]);
            }
            CP_COMMIT();
            CP_WAIT(1);
        } else {
            CP_WAIT(0);
        }
        __syncthreads();

        const int k0 = kt * 64;
        if (q0 + wr + 15 >= k0) {
            const unsigned kb = k_ldm + buf * SKT * 4;
            const unsigned vb = v_ldm + buf * SKT * 4;

            // ---- S = Q @ K^T ----
            float s[8][4];
#pragma unroll
            for (int nt = 0; nt < 8; nt++)
#pragma unroll
                for (int c = 0; c < 4; c++) s[nt][c] = 0.0f;
#pragma unroll
            for (int ks = 0; ks < 8; ks++) {
                const int k8 = ks * 8;
                unsigned bf[8][2];
#pragma unroll
                for (int ntp = 0; ntp < 4; ntp++)
                    LDMATRIX_X4(bf[2 * ntp][0], bf[2 * ntp][1],
                                bf[2 * ntp + 1][0], bf[2 * ntp + 1][1],
                                kb + (ntp * 16 * 68 + k8) * 4);
#pragma unroll
                for (int nt = 0; nt < 8; nt++)
                    MMA_TF32(s[nt], qf[ks], bf[nt]);
            }

            // ---- Scale + causal mask ----
            const bool diag = (kt >= 2 * qt);
            const int rg0 = q0 + wr + g;
            const int rg1 = rg0 + 8;
#pragma unroll
            for (int nt = 0; nt < 8; nt++) {
                const int cg = k0 + nt * 8 + 2 * t4;
                s[nt][0] *= 0.125f; s[nt][1] *= 0.125f;
                s[nt][2] *= 0.125f; s[nt][3] *= 0.125f;
                if (diag) {
                    if (cg > rg0)     s[nt][0] = -1e9f;
                    if (cg + 1 > rg0) s[nt][1] = -1e9f;
                    if (cg > rg1)     s[nt][2] = -1e9f;
                    if (cg + 1 > rg1) s[nt][3] = -1e9f;
                }
            }

            // ---- Online softmax in registers ----
            float mx0 = -1e30f, mx1 = -1e30f;
#pragma unroll
            for (int nt = 0; nt < 8; nt++) {
                mx0 = fmaxf(mx0, fmaxf(s[nt][0], s[nt][1]));
                mx1 = fmaxf(mx1, fmaxf(s[nt][2], s[nt][3]));
            }
            mx0 = fmaxf(mx0, __shfl_xor_sync(0xffffffffu, mx0, 1));
            mx0 = fmaxf(mx0, __shfl_xor_sync(0xffffffffu, mx0, 2));
            mx1 = fmaxf(mx1, __shfl_xor_sync(0xffffffffu, mx1, 1));
            mx1 = fmaxf(mx1, __shfl_xor_sync(0xffffffffu, mx1, 2));

            const float m0n = fmaxf(m0, mx0);
            const float m1n = fmaxf(m1, mx1);
            const float al0 = __expf(m0 - m0n);
            const float al1 = __expf(m1 - m1n);

            float sum0 = 0.0f, sum1 = 0.0f;
#pragma unroll
            for (int nt = 0; nt < 8; nt++) {
                s[nt][0] = __expf(s[nt][0] - m0n);
                s[nt][1] = __expf(s[nt][1] - m0n);
                s[nt][2] = __expf(s[nt][2] - m1n);
                s[nt][3] = __expf(s[nt][3] - m1n);
                sum0 += s[nt][0] + s[nt][1];
                sum1 += s[nt][2] + s[nt][3];
            }
            sum0 += __shfl_xor_sync(0xffffffffu, sum0, 1);
            sum0 += __shfl_xor_sync(0xffffffffu, sum0, 2);
            sum1 += __shfl_xor_sync(0xffffffffu, sum1, 1);
            sum1 += __shfl_xor_sync(0xffffffffu, sum1, 2);

            l0 = l0 * al0 + sum0;
            l1 = l1 * al1 + sum1;
            m0 = m0n; m1 = m1n;

#pragma unroll
            for (int nt = 0; nt < 8; nt++) {
                o[nt][0] *= al0; o[nt][1] *= al0;
                o[nt][2] *= al1; o[nt][3] *= al1;
            }

            // ---- Stage P (tf32) in warp-private sP rows ----
#pragma unroll
            for (int nt = 0; nt < 8; nt++) {
                const int c2 = nt * 8 + 2 * t4;
                sP[(wr + g) * 68 + c2]     = f2tf32(s[nt][0]);
                sP[(wr + g) * 68 + c2 + 1] = f2tf32(s[nt][1]);
                sP[(wr + g + 8) * 68 + c2]     = f2tf32(s[nt][2]);
                sP[(wr + g + 8) * 68 + c2 + 1] = f2tf32(s[nt][3]);
            }
            __syncwarp();

            // ---- O += P @ V  (V b-frags via ldmatrix on sVt) ----
#pragma unroll
            for (int ks = 0; ks < 8; ks++) {
                const int k8 = ks * 8;
                unsigned a[4];
                LDMATRIX_X4(a[0], a[1], a[2], a[3], p_ldm + k8 * 4);
                unsigned bf[8][2];
#pragma unroll
                for (int ntp = 0; ntp < 4; ntp++)
                    LDMATRIX_X4(bf[2 * ntp][0], bf[2 * ntp][1],
                                bf[2 * ntp + 1][0], bf[2 * ntp + 1][1],
                                vb + (ntp * 16 * 68 + k8) * 4);
#pragma unroll
                for (int nt = 0; nt < 8; nt++)
                    MMA_TF32(o[nt], a, bf[nt]);
            }
        }
        __syncthreads();
    }

    // ---- Normalize and store merged-head output as tf32 bits ----
    const float inv0 = 1.0f / l0;
    const float inv1 = 1.0f / l1;
    const size_t r0 = rowbase + q0 + wr + g;
#pragma unroll
    for (int nt = 0; nt < 8; nt++) {
        const int col = h * HDIM + nt * 8 + 2 * t4;
        uint2 v0, v1;
        v0.x = f2tf32(o[nt][0] * inv0); v0.y = f2tf32(o[nt][1] * inv0);
        v1.x = f2tf32(o[nt][2] * inv1); v1.y = f2tf32(o[nt][3] * inv1);
        *(uint2*)&att[r0 * DMODEL + col] = v0;
        *(uint2*)&att[(r0 + 8) * DMODEL + col] = v1;
    }
}

// ---------------------------------------------------------------------------
// Launch
// ---------------------------------------------------------------------------
extern "C" void kernel_launch(void* const* d_in, const int* in_sizes, int n_in,
                              void* d_out, int out_size)
{
    const float* x      = (const float*)d_in[0];  // [2,2048,1024]
    const float* W_qkv  = (const float*)d_in[1];  // [1024,3072]
    const float* b_qkv  = (const float*)d_in[2];  // [3072]
    const float* W_proj = (const float*)d_in[3];  // [1024,1024]
    const float* b_proj = (const float*)d_in[4];  // [1024]
    float* out          = (float*)d_out;          // [2,2048,1024]

    unsigned *x32_buf, *qkv_buf, *vT_buf, *att_buf, *wqkvT, *wprojT;
    cudaGetSymbolAddress((void**)&x32_buf, g_x32);
    cudaGetSymbolAddress((void**)&qkv_buf, g_qkv);
    cudaGetSymbolAddress((void**)&vT_buf,  g_vT);
    cudaGetSymbolAddress((void**)&att_buf, g_att);
    cudaGetSymbolAddress((void**)&wqkvT,  g_wqkvT);
    cudaGetSymbolAddress((void**)&wprojT, g_wprojT);

    cudaFuncSetAttribute(gemm_tf32_kernel<true>,
                         cudaFuncAttributeMaxDynamicSharedMemorySize,
                         GEMM_SMEM_BYTES);
    cudaFuncSetAttribute(gemm_tf32_kernel<false>,
                         cudaFuncAttributeMaxDynamicSharedMemorySize,
                         GEMM_SMEM_BYTES);
    cudaFuncSetAttribute(flash_attn_tf32_kernel,
                         cudaFuncAttributeMaxDynamicSharedMemorySize,
                         SMEM_ATT_BYTES);

    // 0) Pre-convert x to tf32 bits; pre-transpose weights to tf32 n-major
    {
        const int n4 = ROWS * DMODEL / 4;
        cvt_x_kernel<<<(n4 + 255) / 256, 256>>>(
            (const float4*)x, (uint4*)x32_buf, n4);
        dim3 blk(32, 8);
        dim3 g1(QKVCOLS / 32, DMODEL / 32);
        transpose_tf32_kernel<<<g1, blk>>>(W_qkv, wqkvT, DMODEL, QKVCOLS);
        dim3 g2(DMODEL / 32, DMODEL / 32);
        transpose_tf32_kernel<<<g2, blk>>>(W_proj, wprojT, DMODEL, DMODEL);
    }

    // 1) QKV projection -> tf32 qkv buffer (Q,K) + transposed V buffer
    {
        dim3 grid(QKVCOLS / 128, ROWS / 128);
        gemm_tf32_kernel<true><<<grid, 256, GEMM_SMEM_BYTES>>>(
            x32_buf, wqkvT, b_qkv, qkv_buf, vT_buf, ROWS, QKVCOLS, DMODEL);
    }

    // 2) Causal flash attention -> tf32 att buffer
    {
        dim3 grid(SEQ / 128, BATCH * NHEADS);
        flash_attn_tf32_kernel<<<grid, 256, SMEM_ATT_BYTES>>>(
            qkv_buf, vT_buf, att_buf);
    }

    // 3) Output projection -> fp32 out
    {
        dim3 grid(DMODEL / 128, ROWS / 128);
        gemm_tf32_kernel<false><<<grid, 256, GEMM_SMEM_BYTES>>>(
            att_buf, wprojT, b_proj, out, nullptr, ROWS, DMODEL, DMODEL);
    }
}

// round 16
// speedup vs baseline: 1.0371x; 1.0182x over previous
#include <cuda_runtime.h>
#include <math.h>

// Problem constants (fixed by the reference)
#define BATCH   2
#define SEQ     2048
#define DMODEL  1024
#define NHEADS  16
#define HDIM    64
#define ROWS    (BATCH * SEQ)        // 4096
#define QKVCOLS (3 * DMODEL)         // 3072

// Scratch (static device globals — allocation-free per harness rules)
__device__ unsigned g_x32[(size_t)ROWS * DMODEL];       // 16 MB (x as tf32 bits)
__device__ unsigned g_qkv[(size_t)ROWS * QKVCOLS];      // 50 MB (tf32 bits; V third unused)
__device__ unsigned g_vT[(size_t)DMODEL * ROWS];        // 16 MB (tf32 bits, [d_global][row])
__device__ unsigned g_att[(size_t)ROWS * DMODEL];       // 16 MB (tf32 bits)
__device__ unsigned g_wqkvT[(size_t)QKVCOLS * DMODEL];  // 12.6 MB (tf32 bits)
__device__ unsigned g_wprojT[(size_t)DMODEL * DMODEL];  // 4.2 MB  (tf32 bits)

// ---------------------------------------------------------------------------
// Helpers
// ---------------------------------------------------------------------------
__device__ __forceinline__ unsigned f2tf32(float x) {
    unsigned r;
    asm("cvt.rna.tf32.f32 %0, %1;" : "=r"(r) : "f"(x));
    return r;
}

__device__ __forceinline__ float ex2f(float x) {   // 2^x, same HW op __expf uses
    float y;
    asm("ex2.approx.ftz.f32 %0, %1;" : "=f"(y) : "f"(x));
    return y;
}

// D += A(16x8) * B(8x8), tf32 inputs, fp32 accumulate
#define MMA_TF32(d, a, b)                                                     \
    asm volatile(                                                             \
        "mma.sync.aligned.m16n8k8.row.col.f32.tf32.tf32.f32 "                 \
        "{%0,%1,%2,%3},{%4,%5,%6,%7},{%8,%9},{%0,%1,%2,%3};"                  \
        : "+f"((d)[0]), "+f"((d)[1]), "+f"((d)[2]), "+f"((d)[3])              \
        : "r"((a)[0]), "r"((a)[1]), "r"((a)[2]), "r"((a)[3]),                 \
          "r"((b)[0]), "r"((b)[1]))

#define LDMATRIX_X4(r0, r1, r2, r3, addr)                                     \
    asm volatile(                                                             \
        "ldmatrix.sync.aligned.m8n8.x4.shared.b16 {%0,%1,%2,%3}, [%4];"       \
        : "=r"(r0), "=r"(r1), "=r"(r2), "=r"(r3) : "r"(addr))

__device__ __forceinline__ unsigned smem_u32(const void* p) {
    return (unsigned)__cvta_generic_to_shared(p);
}

__device__ __forceinline__ void cp_async16(unsigned dst, const void* src) {
    asm volatile("cp.async.cg.shared.global [%0], [%1], 16;"
                 :: "r"(dst), "l"(src));
}
#define CP_COMMIT() asm volatile("cp.async.commit_group;")
#define CP_WAIT(n)  asm volatile("cp.async.wait_group %0;" :: "n"(n))

// Softmax works in the exp2 domain: s2 = (QK) * (0.125 * log2e).
#define SCALE_L2E 0.18033688f
#define NEG_L2E   (-1.4426951e9f)

// ---------------------------------------------------------------------------
// x pre-convert: fp32 -> tf32 bits (vectorized)
// ---------------------------------------------------------------------------
__global__ void cvt_x_kernel(const float4* __restrict__ x,
                             uint4* __restrict__ x32, int n4)
{
    int i = blockIdx.x * blockDim.x + threadIdx.x;
    if (i < n4) {
        float4 v = x[i];
        uint4 u;
        u.x = f2tf32(v.x); u.y = f2tf32(v.y);
        u.z = f2tf32(v.z); u.w = f2tf32(v.w);
        x32[i] = u;
    }
}

// ---------------------------------------------------------------------------
// Weight pre-transpose: W[K][N] (f32) -> Wt[N][K] (tf32 bits)
// ---------------------------------------------------------------------------
__global__ void transpose_tf32_kernel(const float* __restrict__ W,
                                      unsigned* __restrict__ Wt,
                                      int K, int N)
{
    __shared__ unsigned t[32][33];
    const int x = blockIdx.x * 32 + threadIdx.x;   // n
    const int y = blockIdx.y * 32;                 // k base
#pragma unroll
    for (int j = threadIdx.y; j < 32; j += 8)
        t[j][threadIdx.x] = f2tf32(W[(size_t)(y + j) * N + x]);
    __syncthreads();
    const int xo = blockIdx.y * 32 + threadIdx.x;  // k
    const int yo = blockIdx.x * 32;                // n base
#pragma unroll
    for (int j = threadIdx.y; j < 32; j += 8)
        Wt[(size_t)(yo + j) * K + xo] = t[threadIdx.x][j];
}

// ---------------------------------------------------------------------------
// TF32 tensor-core GEMM: C[M,N] = A[M,K] @ W[K,N] + bias[N].
// A32 (tf32 bits, m-major), Wt (tf32 bits, n-major) — loader is raw uint4
// copies, zero cvt. Register-staged double buffer, ONE __syncthreads/K-tile.
// ---------------------------------------------------------------------------
#define GEMM_BUF   (128 * 36)
#define GEMM_SMEM_BYTES (4 * GEMM_BUF * 4)

template <bool OUT_TF32>
__global__ __launch_bounds__(256, 2)
void gemm_tf32_kernel(const unsigned* __restrict__ A32,
                      const unsigned* __restrict__ Wt,
                      const float* __restrict__ bias,
                      void* __restrict__ Cv,
                      unsigned* __restrict__ vT,
                      int M, int N, int K)
{
    extern __shared__ unsigned gsm[];
    unsigned* As = gsm;                  // [2][128][36]
    unsigned* Bs = gsm + 2 * GEMM_BUF;   // [2][128][36]

    const int tid  = threadIdx.x;
    const int lane = tid & 31;
    const int warp = tid >> 5;
    const int wm   = (warp >> 1) * 32;
    const int wn   = (warp & 1) * 64;
    const int row0 = blockIdx.y * 128;
    const int col0 = blockIdx.x * 128;

    float acc[2][8][4];
#pragma unroll
    for (int mt = 0; mt < 2; mt++)
#pragma unroll
        for (int nt = 0; nt < 8; nt++)
#pragma unroll
            for (int c = 0; c < 4; c++) acc[mt][nt][c] = 0.0f;

    const int lr = tid >> 3;             // 0..31 (+32p)
    const int lc = (tid & 7) * 4;        // k-col
    const unsigned* Ap = A32 + (size_t)(row0 + lr) * K + lc;
    const unsigned* Bp = Wt  + (size_t)(col0 + lr) * K + lc;

    const unsigned aRow = (lane & 15);
    const unsigned aCol = (lane >> 4) * 4;
    const unsigned a_ldm = smem_u32(As) + ((wm + aRow) * 36 + aCol) * 4;
    const unsigned bRow = (lane & 7) + ((lane & 16) >> 1);
    const unsigned bCol = (lane & 8) ? 4u : 0u;
    const unsigned b_ldm = smem_u32(Bs) + ((wn + bRow) * 36 + bCol) * 4;

    // Load first K-tile into buffer 0 (raw copies)
    {
#pragma unroll
        for (int p = 0; p < 4; p++) {
            *(uint4*)&As[(lr + p * 32) * 36 + lc] =
                *(const uint4*)(Ap + (size_t)(p * 32) * K);
            *(uint4*)&Bs[(lr + p * 32) * 36 + lc] =
                *(const uint4*)(Bp + (size_t)(p * 32) * K);
        }
    }
    __syncthreads();

    int cur = 0;
    for (int k0 = 0; k0 < K; k0 += 32) {
        const int k1 = k0 + 32;
        uint4 stA[4], stB[4];
        if (k1 < K) {
#pragma unroll
            for (int p = 0; p < 4; p++) {
                stA[p] = *(const uint4*)(Ap + k1 + (size_t)(p * 32) * K);
                stB[p] = *(const uint4*)(Bp + k1 + (size_t)(p * 32) * K);
            }
        }

        const unsigned aBuf = a_ldm + cur * GEMM_BUF * 4;
        const unsigned bBuf = b_ldm + cur * GEMM_BUF * 4;
#pragma unroll
        for (int ks = 0; ks < 4; ks++) {
            const int k8 = ks * 8;
            unsigned af[2][4];
#pragma unroll
            for (int mt = 0; mt < 2; mt++)
                LDMATRIX_X4(af[mt][0], af[mt][1], af[mt][2], af[mt][3],
                            aBuf + (mt * 16 * 36 + k8) * 4);
            unsigned bf[8][2];
#pragma unroll
            for (int ntp = 0; ntp < 4; ntp++)
                LDMATRIX_X4(bf[2 * ntp][0], bf[2 * ntp][1],
                            bf[2 * ntp + 1][0], bf[2 * ntp + 1][1],
                            bBuf + (ntp * 16 * 36 + k8) * 4);
#pragma unroll
            for (int mt = 0; mt < 2; mt++)
#pragma unroll
                for (int nt = 0; nt < 8; nt++)
                    MMA_TF32(acc[mt][nt], af[mt], bf[nt]);
        }

        if (k1 < K) {
            unsigned* An = As + (cur ^ 1) * GEMM_BUF;
            unsigned* Bn = Bs + (cur ^ 1) * GEMM_BUF;
#pragma unroll
            for (int p = 0; p < 4; p++) {
                *(uint4*)&An[(lr + p * 32) * 36 + lc] = stA[p];
                *(uint4*)&Bn[(lr + p * 32) * 36 + lc] = stB[p];
            }
        }
        __syncthreads();
        cur ^= 1;
    }

    // Epilogue: bias + stores
    const int g  = lane >> 2;
    const int t4 = lane & 3;
    const bool isV = OUT_TF32 && (col0 >= 2 * DMODEL);
#pragma unroll
    for (int mt = 0; mt < 2; mt++) {
        const int rA = row0 + wm + mt * 16 + g;
#pragma unroll
        for (int nt = 0; nt < 8; nt++) {
            const int c = col0 + wn + nt * 8 + 2 * t4;
            const float2 bv = *(const float2*)&bias[c];
            if (OUT_TF32) {
                if (isV) {
                    // transposed store: vT[d_global][row]
                    const int c2 = c - 2 * DMODEL;
                    vT[(size_t)c2 * ROWS + rA]           = f2tf32(acc[mt][nt][0] + bv.x);
                    vT[(size_t)(c2 + 1) * ROWS + rA]     = f2tf32(acc[mt][nt][1] + bv.y);
                    vT[(size_t)c2 * ROWS + rA + 8]       = f2tf32(acc[mt][nt][2] + bv.x);
                    vT[(size_t)(c2 + 1) * ROWS + rA + 8] = f2tf32(acc[mt][nt][3] + bv.y);
                } else {
                    unsigned* C = (unsigned*)Cv;
                    uint2 o0, o1;
                    o0.x = f2tf32(acc[mt][nt][0] + bv.x);
                    o0.y = f2tf32(acc[mt][nt][1] + bv.y);
                    o1.x = f2tf32(acc[mt][nt][2] + bv.x);
                    o1.y = f2tf32(acc[mt][nt][3] + bv.y);
                    *(uint2*)&C[(size_t)rA * N + c] = o0;
                    *(uint2*)&C[(size_t)(rA + 8) * N + c] = o1;
                }
            } else {
                float* C = (float*)Cv;
                float2 o0, o1;
                o0.x = acc[mt][nt][0] + bv.x;
                o0.y = acc[mt][nt][1] + bv.y;
                o1.x = acc[mt][nt][2] + bv.x;
                o1.y = acc[mt][nt][3] + bv.y;
                *(float2*)&C[(size_t)rA * N + c] = o0;
                *(float2*)&C[(size_t)(rA + 8) * N + c] = o1;
            }
        }
    }
}

// ---------------------------------------------------------------------------
// Flash attention: BQ=128, BK=64, 8 warps; Q,K from qkv (tf32 bits),
// V from vT[d_global][row] (tf32 bits, n-major -> ldmatrix b-frags).
// cp.async double-buffered K/V. Softmax runs in the exp2 domain
// (scores pre-scaled by 0.125*log2e; ex2.approx replaces __expf chains).
// Output stored as tf32 bits (proj consumes).
//   sK[2][64][68], sVt[2][64][68] (rows=d, cols=token), sP[128][68]
// ---------------------------------------------------------------------------
#define SKT (64 * 68)
#define SMEM_ATT_BYTES ((4 * SKT + 128 * 68) * 4)

__global__ __launch_bounds__(256, 2)
void flash_attn_tf32_kernel(const unsigned* __restrict__ qkv,
                            const unsigned* __restrict__ vT,
                            unsigned* __restrict__ att)
{
    extern __shared__ unsigned asm_[];
    unsigned* sK  = asm_;                // [2][64][68]
    unsigned* sVt = sK + 2 * SKT;        // [2][64][68] rows=d, cols=token
    unsigned* sP  = sVt + 2 * SKT;       // [128][68]   (Q staging, then P)

    const int tid  = threadIdx.x;
    const int lane = tid & 31;
    const int warp = tid >> 5;           // 0..7 -> rows [16w,16w+16)
    const int g    = lane >> 2;
    const int t4   = lane & 3;
    const int wr   = warp * 16;

    const int bh = blockIdx.y;
    const int b  = bh / NHEADS;
    const int h  = bh % NHEADS;
    const int qt = gridDim.x - 1 - blockIdx.x;   // heavy tiles first
    const int q0 = qt * 128;

    const size_t rowbase = (size_t)b * SEQ;
    const int qcol = h * HDIM;
    const int kcol = DMODEL + h * HDIM;
    const unsigned* vTh = vT + (size_t)h * HDIM * ROWS + rowbase;

    // ldmatrix base addresses (same lane mapping for K and Vt)
    const unsigned nRow = (lane & 7) + ((lane & 16) >> 1);
    const unsigned nColOff = (lane & 8) ? 4u : 0u;
    const unsigned k_ldm = smem_u32(sK)  + (nRow * 68 + nColOff) * 4;
    const unsigned v_ldm = smem_u32(sVt) + (nRow * 68 + nColOff) * 4;
    const unsigned pRow = wr + (lane & 15);
    const unsigned pColOff = (lane >> 4) * 4;
    const unsigned p_ldm = smem_u32(sP) + (pRow * 68 + pColOff) * 4;

    // Loader coords (16B per thread per pass; 4 passes cover 64x64)
    const int lvr = tid >> 4;            // 0..15 (+16 per pass)
    const int lvc = (tid & 15) * 4;      // 0..60
    const unsigned sKb = smem_u32(sK);
    const unsigned sVb = smem_u32(sVt);

    // ---- Stage Q tile into sP (raw tf32 bits) ----
    for (int i = tid; i < 128 * 16; i += 256) {
        const int r  = i >> 4;
        const int c4 = (i & 15) * 4;
        *(uint4*)&sP[r * 68 + c4] =
            *(const uint4*)&qkv[(rowbase + q0 + r) * QKVCOLS + qcol + c4];
    }

    // ---- Prologue: async-load K/V tile 0 into buffer 0 ----
    {
#pragma unroll
        for (int p = 0; p < 4; p++) {
            const int r = lvr + p * 16;
            cp_async16(sKb + (r * 68 + lvc) * 4,
                       &qkv[(rowbase + r) * QKVCOLS + kcol + lvc]);
            cp_async16(sVb + (r * 68 + lvc) * 4,
                       &vTh[(size_t)r * ROWS + lvc]);
        }
        CP_COMMIT();
    }
    __syncthreads();   // sP (Q) visible to all warps

    // Q a-frags via ldmatrix
    unsigned qf[8][4];
#pragma unroll
    for (int ks = 0; ks < 8; ks++)
        LDMATRIX_X4(qf[ks][0], qf[ks][1], qf[ks][2], qf[ks][3],
                    p_ldm + ks * 8 * 4);

    float m0 = -1e30f, m1 = -1e30f, l0 = 0.0f, l1 = 0.0f;
    float o[8][4];
#pragma unroll
    for (int nt = 0; nt < 8; nt++)
#pragma unroll
        for (int c = 0; c < 4; c++) o[nt][c] = 0.0f;

    const int n_kt = 2 * qt + 2;
    for (int kt = 0; kt < n_kt; kt++) {
        const int buf = kt & 1;

        // Issue next tile's loads into the other buffer
        if (kt + 1 < n_kt) {
            const int k0n = (kt + 1) * 64;
            const unsigned sKn = sKb + (buf ^ 1) * SKT * 4;
            const unsigned sVn = sVb + (buf ^ 1) * SKT * 4;
#pragma unroll
            for (int p = 0; p < 4; p++) {
                const int r = lvr + p * 16;
                cp_async16(sKn + (r * 68 + lvc) * 4,
                           &qkv[(rowbase + k0n + r) * QKVCOLS + kcol + lvc]);
                cp_async16(sVn + (r * 68 + lvc) * 4,
                           &vTh[(size_t)r * ROWS + k0n + lvc]);
            }
            CP_COMMIT();
            CP_WAIT(1);
        } else {
            CP_WAIT(0);
        }
        __syncthreads();

        const int k0 = kt * 64;
        if (q0 + wr + 15 >= k0) {
            const unsigned kb = k_ldm + buf * SKT * 4;
            const unsigned vb = v_ldm + buf * SKT * 4;

            // ---- S = Q @ K^T ----
            float s[8][4];
#pragma unroll
            for (int nt = 0; nt < 8; nt++)
#pragma unroll
                for (int c = 0; c < 4; c++) s[nt][c] = 0.0f;
#pragma unroll
            for (int ks = 0; ks < 8; ks++) {
                const int k8 = ks * 8;
                unsigned bf[8][2];
#pragma unroll
                for (int ntp = 0; ntp < 4; ntp++)
                    LDMATRIX_X4(bf[2 * ntp][0], bf[2 * ntp][1],
                                bf[2 * ntp + 1][0], bf[2 * ntp + 1][1],
                                kb + (ntp * 16 * 68 + k8) * 4);
#pragma unroll
                for (int nt = 0; nt < 8; nt++)
                    MMA_TF32(s[nt], qf[ks], bf[nt]);
            }

            // ---- Scale into exp2 domain + causal mask ----
            const bool diag = (kt >= 2 * qt);
            const int rg0 = q0 + wr + g;
            const int rg1 = rg0 + 8;
#pragma unroll
            for (int nt = 0; nt < 8; nt++) {
                const int cg = k0 + nt * 8 + 2 * t4;
                s[nt][0] *= SCALE_L2E; s[nt][1] *= SCALE_L2E;
                s[nt][2] *= SCALE_L2E; s[nt][3] *= SCALE_L2E;
                if (diag) {
                    if (cg > rg0)     s[nt][0] = NEG_L2E;
                    if (cg + 1 > rg0) s[nt][1] = NEG_L2E;
                    if (cg > rg1)     s[nt][2] = NEG_L2E;
                    if (cg + 1 > rg1) s[nt][3] = NEG_L2E;
                }
            }

            // ---- Online softmax in registers (exp2 domain) ----
            float mx0 = -1e30f, mx1 = -1e30f;
#pragma unroll
            for (int nt = 0; nt < 8; nt++) {
                mx0 = fmaxf(mx0, fmaxf(s[nt][0], s[nt][1]));
                mx1 = fmaxf(mx1, fmaxf(s[nt][2], s[nt][3]));
            }
            mx0 = fmaxf(mx0, __shfl_xor_sync(0xffffffffu, mx0, 1));
            mx0 = fmaxf(mx0, __shfl_xor_sync(0xffffffffu, mx0, 2));
            mx1 = fmaxf(mx1, __shfl_xor_sync(0xffffffffu, mx1, 1));
            mx1 = fmaxf(mx1, __shfl_xor_sync(0xffffffffu, mx1, 2));

            const float m0n = fmaxf(m0, mx0);
            const float m1n = fmaxf(m1, mx1);
            const float al0 = ex2f(m0 - m0n);
            const float al1 = ex2f(m1 - m1n);

            float sum0 = 0.0f, sum1 = 0.0f;
#pragma unroll
            for (int nt = 0; nt < 8; nt++) {
                s[nt][0] = ex2f(s[nt][0] - m0n);
                s[nt][1] = ex2f(s[nt][1] - m0n);
                s[nt][2] = ex2f(s[nt][2] - m1n);
                s[nt][3] = ex2f(s[nt][3] - m1n);
                sum0 += s[nt][0] + s[nt][1];
                sum1 += s[nt][2] + s[nt][3];
            }
            sum0 += __shfl_xor_sync(0xffffffffu, sum0, 1);
            sum0 += __shfl_xor_sync(0xffffffffu, sum0, 2);
            sum1 += __shfl_xor_sync(0xffffffffu, sum1, 1);
            sum1 += __shfl_xor_sync(0xffffffffu, sum1, 2);

            l0 = l0 * al0 + sum0;
            l1 = l1 * al1 + sum1;
            m0 = m0n; m1 = m1n;

#pragma unroll
            for (int nt = 0; nt < 8; nt++) {
                o[nt][0] *= al0; o[nt][1] *= al0;
                o[nt][2] *= al1; o[nt][3] *= al1;
            }

            // ---- Stage P (tf32) in warp-private sP rows ----
#pragma unroll
            for (int nt = 0; nt < 8; nt++) {
                const int c2 = nt * 8 + 2 * t4;
                sP[(wr + g) * 68 + c2]     = f2tf32(s[nt][0]);
                sP[(wr + g) * 68 + c2 + 1] = f2tf32(s[nt][1]);
                sP[(wr + g + 8) * 68 + c2]     = f2tf32(s[nt][2]);
                sP[(wr + g + 8) * 68 + c2 + 1] = f2tf32(s[nt][3]);
            }
            __syncwarp();

            // ---- O += P @ V  (V b-frags via ldmatrix on sVt) ----
#pragma unroll
            for (int ks = 0; ks < 8; ks++) {
                const int k8 = ks * 8;
                unsigned a[4];
                LDMATRIX_X4(a[0], a[1], a[2], a[3], p_ldm + k8 * 4);
                unsigned bf[8][2];
#pragma unroll
                for (int ntp = 0; ntp < 4; ntp++)
                    LDMATRIX_X4(bf[2 * ntp][0], bf[2 * ntp][1],
                                bf[2 * ntp + 1][0], bf[2 * ntp + 1][1],
                                vb + (ntp * 16 * 68 + k8) * 4);
#pragma unroll
                for (int nt = 0; nt < 8; nt++)
                    MMA_TF32(o[nt], a, bf[nt]);
            }
        }
        __syncthreads();
    }

    // ---- Normalize and store merged-head output as tf32 bits ----
    const float inv0 = 1.0f / l0;
    const float inv1 = 1.0f / l1;
    const size_t r0 = rowbase + q0 + wr + g;
#pragma unroll
    for (int nt = 0; nt < 8; nt++) {
        const int col = h * HDIM + nt * 8 + 2 * t4;
        uint2 v0, v1;
        v0.x = f2tf32(o[nt][0] * inv0); v0.y = f2tf32(o[nt][1] * inv0);
        v1.x = f2tf32(o[nt][2] * inv1); v1.y = f2tf32(o[nt][3] * inv1);
        *(uint2*)&att[r0 * DMODEL + col] = v0;
        *(uint2*)&att[(r0 + 8) * DMODEL + col] = v1;
    }
}

// ---------------------------------------------------------------------------
// Launch
// ---------------------------------------------------------------------------
extern "C" void kernel_launch(void* const* d_in, const int* in_sizes, int n_in,
                              void* d_out, int out_size)
{
    const float* x      = (const float*)d_in[0];  // [2,2048,1024]
    const float* W_qkv  = (const float*)d_in[1];  // [1024,3072]
    const float* b_qkv  = (const float*)d_in[2];  // [3072]
    const float* W_proj = (const float*)d_in[3];  // [1024,1024]
    const float* b_proj = (const float*)d_in[4];  // [1024]
    float* out          = (float*)d_out;          // [2,2048,1024]

    unsigned *x32_buf, *qkv_buf, *vT_buf, *att_buf, *wqkvT, *wprojT;
    cudaGetSymbolAddress((void**)&x32_buf, g_x32);
    cudaGetSymbolAddress((void**)&qkv_buf, g_qkv);
    cudaGetSymbolAddress((void**)&vT_buf,  g_vT);
    cudaGetSymbolAddress((void**)&att_buf, g_att);
    cudaGetSymbolAddress((void**)&wqkvT,  g_wqkvT);
    cudaGetSymbolAddress((void**)&wprojT, g_wprojT);

    cudaFuncSetAttribute(gemm_tf32_kernel<true>,
                         cudaFuncAttributeMaxDynamicSharedMemorySize,
                         GEMM_SMEM_BYTES);
    cudaFuncSetAttribute(gemm_tf32_kernel<false>,
                         cudaFuncAttributeMaxDynamicSharedMemorySize,
                         GEMM_SMEM_BYTES);
    cudaFuncSetAttribute(flash_attn_tf32_kernel,
                         cudaFuncAttributeMaxDynamicSharedMemorySize,
                         SMEM_ATT_BYTES);

    // 0) Pre-convert x to tf32 bits; pre-transpose weights to tf32 n-major
    {
        const int n4 = ROWS * DMODEL / 4;
        cvt_x_kernel<<<(n4 + 255) / 256, 256>>>(
            (const float4*)x, (uint4*)x32_buf, n4);
        dim3 blk(32, 8);
        dim3 g1(QKVCOLS / 32, DMODEL / 32);
        transpose_tf32_kernel<<<g1, blk>>>(W_qkv, wqkvT, DMODEL, QKVCOLS);
        dim3 g2(DMODEL / 32, DMODEL / 32);
        transpose_tf32_kernel<<<g2, blk>>>(W_proj, wprojT, DMODEL, DMODEL);
    }

    // 1) QKV projection -> tf32 qkv buffer (Q,K) + transposed V buffer
    {
        dim3 grid(QKVCOLS / 128, ROWS / 128);
        gemm_tf32_kernel<true><<<grid, 256, GEMM_SMEM_BYTES>>>(
            x32_buf, wqkvT, b_qkv, qkv_buf, vT_buf, ROWS, QKVCOLS, DMODEL);
    }

    // 2) Causal flash attention -> tf32 att buffer
    {
        dim3 grid(SEQ / 128, BATCH * NHEADS);
        flash_attn_tf32_kernel<<<grid, 256, SMEM_ATT_BYTES>>>(
            qkv_buf, vT_buf, att_buf);
    }

    // 3) Output projection -> fp32 out
    {
        dim3 grid(DMODEL / 128, ROWS / 128);
        gemm_tf32_kernel<false><<<grid, 256, GEMM_SMEM_BYTES>>>(
            att_buf, wprojT, b_proj, out, nullptr, ROWS, DMODEL, DMODEL);
    }
}